// round 15
// baseline (speedup 1.0000x reference)
#include <cuda_runtime.h>
#include <cuda_fp16.h>
#include <math.h>
#include <stdint.h>

// Problem constants
#define S    2048
#define D    2048
#define NH   32
#define NKV  8
#define HD   64
#define QKV_N 3072   // (32 + 16) * 64

// ---------------------------------------------------------------------------
// Scratch (device globals — no allocation allowed)
// ---------------------------------------------------------------------------
__device__ __half g_qkvh [(size_t)S * QKV_N];     // [s, 3072] fp16 qkv
__device__ __half g_hsh  [(size_t)S * D];         // hs in fp16
__device__ __half g_wqkvh[(size_t)QKV_N * D];     // wqkv in fp16
__device__ __half g_woh  [(size_t)D * D];         // wo in fp16
__device__ __half g_qh [(size_t)NH  * S * HD];    // [h, s, d] (pre-scaled)
__device__ __half g_kh [(size_t)NKV * S * HD];    // [kh, s, d]
__device__ __half g_vth[(size_t)NKV * HD * S];    // [kh, d, s] (transposed)
__device__ __half g_attnh[(size_t)S * D];         // attention out, fp16

__device__ __forceinline__ void mma_f16(float* d, const uint32_t* a,
                                        uint32_t b0, uint32_t b1) {
    asm volatile(
        "mma.sync.aligned.m16n8k16.row.col.f32.f16.f16.f32 "
        "{%0,%1,%2,%3}, {%4,%5,%6,%7}, {%8,%9}, {%0,%1,%2,%3};"
        : "+f"(d[0]), "+f"(d[1]), "+f"(d[2]), "+f"(d[3])
        : "r"(a[0]), "r"(a[1]), "r"(a[2]), "r"(a[3]), "r"(b0), "r"(b1));
}

__device__ __forceinline__ void ldsm_x4(uint32_t* r, uint32_t addr) {
    asm volatile("ldmatrix.sync.aligned.m8n8.x4.shared.b16 {%0,%1,%2,%3}, [%4];"
                 : "=r"(r[0]), "=r"(r[1]), "=r"(r[2]), "=r"(r[3]) : "r"(addr));
}

__device__ __forceinline__ void cp16(uint32_t dst, const void* src) {
    asm volatile("cp.async.cg.shared.global [%0], [%1], 16;" :: "r"(dst), "l"(src));
}
#define CP_COMMIT() asm volatile("cp.async.commit_group;" ::: "memory")
#define CP_WAIT0()  asm volatile("cp.async.wait_group 0;" ::: "memory")

__device__ __forceinline__ uint32_t ex2_h2(uint32_t x) {
    uint32_t r;
    asm("ex2.approx.f16x2 %0, %1;" : "=r"(r) : "r"(x));
    return r;
}
__device__ __forceinline__ uint32_t pack_h2(float lo, float hi) {
    __half2 h = __floats2half2_rn(lo, hi);
    return *(uint32_t*)&h;
}

// ---------------------------------------------------------------------------
// fused f32 -> f16 conversion of hs, wqkv, wo
// ---------------------------------------------------------------------------
#define N4_HS   (S * D / 4)
#define N4_WQKV (QKV_N * D / 4)
#define N4_WO   (D * D / 4)
#define N4_ALL  (N4_HS + N4_WQKV + N4_WO)

__global__ __launch_bounds__(256) void cvt_all(const float* __restrict__ hs,
                                               const float* __restrict__ wqkv,
                                               const float* __restrict__ wo,
                                               __half* __restrict__ hsh,
                                               __half* __restrict__ wqkvh,
                                               __half* __restrict__ woh) {
    int i = blockIdx.x * 256 + threadIdx.x;
    const float* src;
    __half* dst;
    int j;
    if (i < N4_HS)                   { src = hs;   dst = hsh;   j = i; }
    else if (i < N4_HS + N4_WQKV)    { src = wqkv; dst = wqkvh; j = i - N4_HS; }
    else if (i < N4_ALL)             { src = wo;   dst = woh;   j = i - N4_HS - N4_WQKV; }
    else return;
    float4 v = ((const float4*)src)[j];
    __half2 h01 = __floats2half2_rn(v.x, v.y);
    __half2 h23 = __floats2half2_rn(v.z, v.w);
    ((uint2*)dst)[j] = make_uint2(*(uint32_t*)&h01, *(uint32_t*)&h23);
}

// ---------------------------------------------------------------------------
// fp16 tensor-core GEMM: CTA 128x128, 8 warps (2m x 4n), warp tile 64x32,
// k-tile 64 (128B rows), 2-stage cp.async, row-XOR swizzle, ldmatrix.x4.
// HALF_OUT=0: f32 C.  HALF_OUT=1: fp16 C (same layout).
// ---------------------------------------------------------------------------
#define SWB2(row, b) ((row) * 128 + (((((b) >> 4) ^ ((row) & 7)) << 4) | ((b) & 15)))
#define GSTAGE 16384
#define GSMEM_TOTAL (4 * GSTAGE)

template <int HALF_OUT>
__global__ __launch_bounds__(256) void gemm_h(const __half* __restrict__ A,
                                              const __half* __restrict__ B,
                                              float* __restrict__ C,
                                              __half* __restrict__ Ch,
                                              int M, int N, int K) {
    extern __shared__ __align__(16) char gsm[];

    const int tid  = threadIdx.x;
    const int lane = tid & 31;
    const int wid  = tid >> 5;
    const int wm   = wid >> 2;
    const int wn   = wid & 3;
    const int g    = lane >> 2;
    const int t    = lane & 3;
    const int row0 = blockIdx.y * 128;
    const int col0 = blockIdx.x * 128;

    const uint32_t smb = (uint32_t)__cvta_generic_to_shared(gsm);
    const uint32_t asb = smb;
    const uint32_t bsb = smb + 2 * GSTAGE;

    uint32_t st[4];
    const __half *Ap[4], *Bp[4];
#pragma unroll
    for (int i = 0; i < 4; i++) {
        const int idx = tid + i * 256;
        const int r   = idx >> 3;
        const int ch  = idx & 7;
        st[i] = SWB2(r, ch * 16);
        Ap[i] = A + (size_t)(row0 + r) * K + ch * 8;
        Bp[i] = B + (size_t)(col0 + r) * K + ch * 8;
    }

    const int a_r = wm * 64 + ((lane >> 3) & 1) * 8 + (lane & 7);
    const int a_c = (lane >> 4) * 16;
    const int b_r = wn * 32 + (lane >> 4) * 8 + (lane & 7);
    const int b_c = ((lane >> 3) & 1) * 16;

    float acc[4][4][4];
#pragma unroll
    for (int mi = 0; mi < 4; mi++)
#pragma unroll
        for (int ni = 0; ni < 4; ni++)
#pragma unroll
            for (int e = 0; e < 4; e++) acc[mi][ni][e] = 0.f;

#pragma unroll
    for (int i = 0; i < 4; i++) {
        cp16(asb + st[i], Ap[i]);
        cp16(bsb + st[i], Bp[i]);
    }
    CP_COMMIT();

    const int NT = K / 64;
    int buf = 0;
    for (int it = 0; it < NT; it++) {
        CP_WAIT0();
        __syncthreads();

        if (it + 1 < NT) {
            const int k0 = (it + 1) * 64;
            const uint32_t sb = (buf ^ 1) * GSTAGE;
#pragma unroll
            for (int i = 0; i < 4; i++) {
                cp16(asb + sb + st[i], Ap[i] + k0);
                cp16(bsb + sb + st[i], Bp[i] + k0);
            }
            CP_COMMIT();
        }

        const uint32_t ab = asb + buf * GSTAGE;
        const uint32_t bb = bsb + buf * GSTAGE;
#pragma unroll
        for (int kk2 = 0; kk2 < 4; kk2++) {
            const int kb = kk2 * 32;
            uint32_t af[4][4], bf[2][4];
#pragma unroll
            for (int mi = 0; mi < 4; mi++)
                ldsm_x4(af[mi], ab + SWB2(a_r + mi * 16, kb + a_c));
#pragma unroll
            for (int np = 0; np < 2; np++)
                ldsm_x4(bf[np], bb + SWB2(b_r + np * 16, kb + b_c));
#pragma unroll
            for (int mi = 0; mi < 4; mi++)
#pragma unroll
                for (int ni = 0; ni < 4; ni++)
                    mma_f16(acc[mi][ni], af[mi],
                            bf[ni >> 1][(ni & 1) * 2], bf[ni >> 1][(ni & 1) * 2 + 1]);
        }
        buf ^= 1;
    }

#pragma unroll
    for (int mi = 0; mi < 4; mi++) {
        const int row = row0 + wm * 64 + mi * 16 + g;
#pragma unroll
        for (int ni = 0; ni < 4; ni++) {
            const int col = col0 + wn * 32 + ni * 8 + 2 * t;
            if (HALF_OUT) {
                *(__half2*)&Ch[(size_t)row * N + col] =
                    __floats2half2_rn(acc[mi][ni][0], acc[mi][ni][1]);
                *(__half2*)&Ch[(size_t)(row + 8) * N + col] =
                    __floats2half2_rn(acc[mi][ni][2], acc[mi][ni][3]);
            } else {
                *(float2*)&C[(size_t)row * N + col] =
                    make_float2(acc[mi][ni][0], acc[mi][ni][1]);
                *(float2*)&C[(size_t)(row + 8) * N + col] =
                    make_float2(acc[mi][ni][2], acc[mi][ni][3]);
            }
        }
    }
}

// ---------------------------------------------------------------------------
// RoPE on fp16 qkv -> fp16 attention tensors.
// ---------------------------------------------------------------------------
#define QSCALE 0.18033688011112042f   // 0.125 * log2(e)

__global__ __launch_bounds__(256) void rope_fp16(const __half* __restrict__ qkv,
                                                 const float* __restrict__ fc,
                                                 __half* __restrict__ Qh,
                                                 __half* __restrict__ Kh,
                                                 __half* __restrict__ Vth) {
    const int s   = blockIdx.x;
    const int tid = threadIdx.x;
    const __half* row = qkv + (size_t)s * QKV_N;

    for (int i = tid; i < NH * (HD / 2); i += 256) {
        int h = i >> 5, d2 = i & 31;
        __half2 x = *(const __half2*)&row[h * HD + 2 * d2];
        float x0 = __low2float(x), x1 = __high2float(x);
        float c  = fc[s * HD + 2 * d2];
        float sn = fc[s * HD + 2 * d2 + 1];
        float y0 = (x0 * c - x1 * sn) * QSCALE;
        float y1 = (x1 * c + x0 * sn) * QSCALE;
        *(__half2*)&Qh[((size_t)h * S + s) * HD + 2 * d2] = __floats2half2_rn(y0, y1);
    }
    {
        int h = tid >> 5, d2 = tid & 31;
        __half2 x = *(const __half2*)&row[D + h * HD + 2 * d2];
        float x0 = __low2float(x), x1 = __high2float(x);
        float c  = fc[s * HD + 2 * d2];
        float sn = fc[s * HD + 2 * d2 + 1];
        float y0 = x0 * c - x1 * sn;
        float y1 = x1 * c + x0 * sn;
        *(__half2*)&Kh[((size_t)h * S + s) * HD + 2 * d2] = __floats2half2_rn(y0, y1);
    }
    for (int i = tid; i < NKV * HD; i += 256) {
        int h = i >> 6, d = i & 63;
        Vth[((size_t)h * HD + d) * S + s] = row[D + NKV * HD + i];
    }
}

// ---------------------------------------------------------------------------
// Tensor-core causal flash attention (fp16 mma, fp32 acc, no-max softmax).
// 128-KV-row pipeline stages (2 sub-tiles of 64 computed per stage),
// cp.async double-buffered, ldmatrix.x4 fragment loads.
// Dynamic smem: K 2x128x176B + V 2x64x272B = 79872 B.
// ---------------------------------------------------------------------------
#define AQ 128
#define AK 64                 // compute sub-tile (KV rows)
#define KLD 88                // K row stride in halves (176 B)
#define VLD 136               // V row stride in halves (272 B)
#define KS_STAGE (128 * KLD * 2)      // 22528 B
#define VS_STAGE (64 * VLD * 2)       // 17408 B
#define KS_OFF   0
#define VS_OFF   (2 * KS_STAGE)       // 45056
#define ATT_SMEM (2 * KS_STAGE + 2 * VS_STAGE)   // 79872

__global__ __launch_bounds__(256) void attn_mma(const __half* __restrict__ Qh,
                                                const __half* __restrict__ Kh,
                                                const __half* __restrict__ Vth,
                                                __half* __restrict__ O) {
    extern __shared__ __align__(16) char asm_buf[];

    const int h    = blockIdx.y;
    const int kh   = h >> 2;
    const int qb   = gridDim.x - 1 - blockIdx.x;
    const int tid  = threadIdx.x;
    const int lane = tid & 31;
    const int w    = tid >> 5;
    const int g    = lane >> 2;
    const int t    = lane & 3;
    const int bq   = qb * AQ + w * 16;

    const uint32_t smb = (uint32_t)__cvta_generic_to_shared(asm_buf);
    const uint32_t ksb = smb + KS_OFF;
    const uint32_t vsb = smb + VS_OFF;

    const int f_r = (lane >> 4) * 8 + (lane & 7);
    const int f_c = ((lane >> 3) & 1) * 16;

    uint32_t qf[4][4];
    const __half* Qr0 = Qh + ((size_t)h * S + bq + g) * HD;
    const __half* Qr8 = Qr0 + 8 * HD;
#pragma unroll
    for (int kc = 0; kc < 4; kc++) {
        qf[kc][0] = *(const uint32_t*)(Qr0 + 16 * kc + 2 * t);
        qf[kc][1] = *(const uint32_t*)(Qr8 + 16 * kc + 2 * t);
        qf[kc][2] = *(const uint32_t*)(Qr0 + 16 * kc + 2 * t + 8);
        qf[kc][3] = *(const uint32_t*)(Qr8 + 16 * kc + 2 * t + 8);
    }

    float o[8][4];
#pragma unroll
    for (int nn = 0; nn < 8; nn++)
#pragma unroll
        for (int e = 0; e < 4; e++) o[nn][e] = 0.f;
    float lacc[4] = {0.f, 0.f, 0.f, 0.f};
    const uint32_t ONES = 0x3C003C00u;

    const __half* Kg = Kh  + (size_t)kh * S * HD;
    const __half* Vg = Vth + (size_t)kh * HD * S;

    const int nstages = qb + 1;     // 128 KV rows per stage

    // prologue: stage 0 -> buf 0
    {
#pragma unroll
        for (int i = 0; i < 4; i++) {
            const int idx = tid + i * 256;             // 0..1023
            const int kr = idx >> 3, kc = idx & 7;     // K: 128 rows x 8 chunks
            cp16(ksb + kr * (KLD * 2) + kc * 16, Kg + (size_t)kr * HD + kc * 8);
            const int vr = idx >> 4, vc = idx & 15;    // V: 64 rows x 16 chunks
            cp16(vsb + vr * (VLD * 2) + vc * 16, Vg + (size_t)vr * S + vc * 8);
        }
        CP_COMMIT();
    }

    int buf = 0;
    for (int ss = 0; ss < nstages; ss++) {
        CP_WAIT0();
        __syncthreads();   // stage ss resident; all warps done with buf^1

        if (ss + 1 < nstages) {
            const int nkv = (ss + 1) * 128;
            const uint32_t kd = ksb + (buf ^ 1) * KS_STAGE;
            const uint32_t vd = vsb + (buf ^ 1) * VS_STAGE;
#pragma unroll
            for (int i = 0; i < 4; i++) {
                const int idx = tid + i * 256;
                const int kr = idx >> 3, kc = idx & 7;
                cp16(kd + kr * (KLD * 2) + kc * 16,
                     Kg + (size_t)(nkv + kr) * HD + kc * 8);
                const int vr = idx >> 4, vc = idx & 15;
                cp16(vd + vr * (VLD * 2) + vc * 16,
                     Vg + (size_t)vr * S + nkv + vc * 8);
            }
            CP_COMMIT();
        }

        const uint32_t kb_s = ksb + buf * KS_STAGE;
        const uint32_t vb_s = vsb + buf * VS_STAGE;

#pragma unroll
        for (int hh = 0; hh < 2; hh++) {
            const int kv0 = ss * 128 + hh * AK;
            if (kv0 > bq + 15) continue;   // warp-uniform skip
            const uint32_t kb0 = kb_s + hh * 64 * (KLD * 2);
            const uint32_t vb0 = vb_s + hh * 128;   // 64 kv halves = 128 B

            float sc[8][4];
#pragma unroll
            for (int nn = 0; nn < 8; nn++)
                sc[nn][0] = sc[nn][1] = sc[nn][2] = sc[nn][3] = 0.f;
#pragma unroll
            for (int kc = 0; kc < 4; kc++) {
                uint32_t bf[4][4];
#pragma unroll
                for (int np = 0; np < 4; np++)
                    ldsm_x4(bf[np], kb0 + (np * 16 + f_r) * (KLD * 2) + kc * 32 + f_c);
#pragma unroll
                for (int nn = 0; nn < 8; nn++)
                    mma_f16(sc[nn], qf[kc],
                            bf[nn >> 1][(nn & 1) * 2], bf[nn >> 1][(nn & 1) * 2 + 1]);
            }
            if (kv0 + AK - 1 > bq) {
                const int rg  = bq + g;
                const int rg8 = rg + 8;
#pragma unroll
                for (int nn = 0; nn < 8; nn++) {
                    const int col = kv0 + nn * 8 + 2 * t;
                    if (col     > rg ) sc[nn][0] = -30.f;
                    if (col + 1 > rg ) sc[nn][1] = -30.f;
                    if (col     > rg8) sc[nn][2] = -30.f;
                    if (col + 1 > rg8) sc[nn][3] = -30.f;
                }
            }
            uint32_t p[8][2];
#pragma unroll
            for (int nn = 0; nn < 8; nn++) {
                p[nn][0] = ex2_h2(pack_h2(sc[nn][0], sc[nn][1]));
                p[nn][1] = ex2_h2(pack_h2(sc[nn][2], sc[nn][3]));
            }
#pragma unroll
            for (int c = 0; c < 4; c++) {
                uint32_t a[4] = {p[2 * c][0], p[2 * c][1],
                                 p[2 * c + 1][0], p[2 * c + 1][1]};
                mma_f16(lacc, a, ONES, ONES);
                uint32_t bf[4][4];
#pragma unroll
                for (int np = 0; np < 4; np++)
                    ldsm_x4(bf[np], vb0 + (np * 16 + f_r) * (VLD * 2) + c * 32 + f_c);
#pragma unroll
                for (int nn = 0; nn < 8; nn++)
                    mma_f16(o[nn], a,
                            bf[nn >> 1][(nn & 1) * 2], bf[nn >> 1][(nn & 1) * 2 + 1]);
            }
        }
        buf ^= 1;
    }

    const float invg  = 1.f / lacc[0];
    const float invg8 = 1.f / lacc[2];
#pragma unroll
    for (int nn = 0; nn < 8; nn++) {
        const int col = h * HD + nn * 8 + 2 * t;
        *(__half2*)&O[(size_t)(bq + g) * D + col] =
            __floats2half2_rn(o[nn][0] * invg, o[nn][1] * invg);
        *(__half2*)&O[(size_t)(bq + g + 8) * D + col] =
            __floats2half2_rn(o[nn][2] * invg8, o[nn][3] * invg8);
    }
}

// ---------------------------------------------------------------------------
// Launch
// ---------------------------------------------------------------------------
extern "C" void kernel_launch(void* const* d_in, const int* in_sizes, int n_in,
                              void* d_out, int out_size) {
    const float* hs   = (const float*)d_in[0];   // [1, 2048, 2048]
    const float* fc   = (const float*)d_in[1];   // [2048, 32, 2]
    const float* wqkv = (const float*)d_in[2];   // [3072, 2048]
    const float* wo   = (const float*)d_in[3];   // [2048, 2048]
    float* out = (float*)d_out;                  // [1, 2048, 2048]

    __half *p_qkvh, *p_hsh, *p_wqkvh, *p_woh, *p_qh, *p_kh, *p_vth, *p_attnh;
    cudaGetSymbolAddress((void**)&p_qkvh,  g_qkvh);
    cudaGetSymbolAddress((void**)&p_hsh,   g_hsh);
    cudaGetSymbolAddress((void**)&p_wqkvh, g_wqkvh);
    cudaGetSymbolAddress((void**)&p_woh,   g_woh);
    cudaGetSymbolAddress((void**)&p_qh,    g_qh);
    cudaGetSymbolAddress((void**)&p_kh,    g_kh);
    cudaGetSymbolAddress((void**)&p_vth,   g_vth);
    cudaGetSymbolAddress((void**)&p_attnh, g_attnh);

    cudaFuncSetAttribute(gemm_h<0>, cudaFuncAttributeMaxDynamicSharedMemorySize,
                         GSMEM_TOTAL);
    cudaFuncSetAttribute(gemm_h<1>, cudaFuncAttributeMaxDynamicSharedMemorySize,
                         GSMEM_TOTAL);
    cudaFuncSetAttribute(attn_mma, cudaFuncAttributeMaxDynamicSharedMemorySize,
                         ATT_SMEM);

    // 0) fp16 conversions (single fused kernel)
    cvt_all<<<(N4_ALL + 255) / 256, 256>>>(hs, wqkv, wo, p_hsh, p_wqkvh, p_woh);

    // 1) qkv = hs @ wqkv^T  (fp16 out)
    gemm_h<1><<<dim3(QKV_N / 128, S / 128), 256, GSMEM_TOTAL>>>(
        p_hsh, p_wqkvh, nullptr, p_qkvh, S, QKV_N, D);
    // 2) RoPE -> fp16 Q (pre-scaled), K, V^T
    rope_fp16<<<S, 256>>>(p_qkvh, fc, p_qh, p_kh, p_vth);
    // 3) tensor-core causal attention (fp16 out)
    attn_mma<<<dim3(S / AQ, NH), 256, ATT_SMEM>>>(p_qh, p_kh, p_vth, p_attnh);
    // 4) out = attn @ wo^T  (f32 out)
    gemm_h<0><<<dim3(D / 128, S / 128), 256, GSMEM_TOTAL>>>(
        p_attnh, p_woh, out, nullptr, S, D, D);
}

// round 16
// speedup vs baseline: 1.0988x; 1.0988x over previous
#include <cuda_runtime.h>
#include <cuda_fp16.h>
#include <math.h>
#include <stdint.h>

// Problem constants
#define S    2048
#define D    2048
#define NH   32
#define NKV  8
#define HD   64
#define QKV_N 3072   // (32 + 16) * 64

// ---------------------------------------------------------------------------
// Scratch (device globals — no allocation allowed)
// ---------------------------------------------------------------------------
__device__ __half g_qkvh [(size_t)S * QKV_N];     // [s, 3072] fp16 qkv
__device__ __half g_hsh  [(size_t)S * D];         // hs in fp16
__device__ __half g_wqkvh[(size_t)QKV_N * D];     // wqkv in fp16
__device__ __half g_woh  [(size_t)D * D];         // wo in fp16
__device__ __half g_qh [(size_t)NH  * S * HD];    // [h, s, d] (pre-scaled)
__device__ __half g_kh [(size_t)NKV * S * HD];    // [kh, s, d]
__device__ __half g_vth[(size_t)NKV * HD * S];    // [kh, d, s] (transposed)
__device__ __half g_attnh[(size_t)S * D];         // attention out, fp16

__device__ __forceinline__ void mma_f16(float* d, const uint32_t* a,
                                        uint32_t b0, uint32_t b1) {
    asm volatile(
        "mma.sync.aligned.m16n8k16.row.col.f32.f16.f16.f32 "
        "{%0,%1,%2,%3}, {%4,%5,%6,%7}, {%8,%9}, {%0,%1,%2,%3};"
        : "+f"(d[0]), "+f"(d[1]), "+f"(d[2]), "+f"(d[3])
        : "r"(a[0]), "r"(a[1]), "r"(a[2]), "r"(a[3]), "r"(b0), "r"(b1));
}

__device__ __forceinline__ void ldsm_x4(uint32_t* r, uint32_t addr) {
    asm volatile("ldmatrix.sync.aligned.m8n8.x4.shared.b16 {%0,%1,%2,%3}, [%4];"
                 : "=r"(r[0]), "=r"(r[1]), "=r"(r[2]), "=r"(r[3]) : "r"(addr));
}

__device__ __forceinline__ void cp16(uint32_t dst, const void* src) {
    asm volatile("cp.async.cg.shared.global [%0], [%1], 16;" :: "r"(dst), "l"(src));
}
#define CP_COMMIT() asm volatile("cp.async.commit_group;" ::: "memory")
#define CP_WAIT0()  asm volatile("cp.async.wait_group 0;" ::: "memory")

__device__ __forceinline__ uint32_t ex2_h2(uint32_t x) {
    uint32_t r;
    asm("ex2.approx.f16x2 %0, %1;" : "=r"(r) : "r"(x));
    return r;
}
__device__ __forceinline__ uint32_t pack_h2(float lo, float hi) {
    __half2 h = __floats2half2_rn(lo, hi);
    return *(uint32_t*)&h;
}

// ---------------------------------------------------------------------------
// fused f32 -> f16 conversion of hs, wqkv, wo
// ---------------------------------------------------------------------------
#define N4_HS   (S * D / 4)
#define N4_WQKV (QKV_N * D / 4)
#define N4_WO   (D * D / 4)
#define N4_ALL  (N4_HS + N4_WQKV + N4_WO)

__global__ __launch_bounds__(256) void cvt_all(const float* __restrict__ hs,
                                               const float* __restrict__ wqkv,
                                               const float* __restrict__ wo,
                                               __half* __restrict__ hsh,
                                               __half* __restrict__ wqkvh,
                                               __half* __restrict__ woh) {
    int i = blockIdx.x * 256 + threadIdx.x;
    const float* src;
    __half* dst;
    int j;
    if (i < N4_HS)                   { src = hs;   dst = hsh;   j = i; }
    else if (i < N4_HS + N4_WQKV)    { src = wqkv; dst = wqkvh; j = i - N4_HS; }
    else if (i < N4_ALL)             { src = wo;   dst = woh;   j = i - N4_HS - N4_WQKV; }
    else return;
    float4 v = ((const float4*)src)[j];
    __half2 h01 = __floats2half2_rn(v.x, v.y);
    __half2 h23 = __floats2half2_rn(v.z, v.w);
    ((uint2*)dst)[j] = make_uint2(*(uint32_t*)&h01, *(uint32_t*)&h23);
}

// ---------------------------------------------------------------------------
// fp16 tensor-core GEMM: CTA 128x128, 8 warps (2m x 4n), warp tile 64x32,
// k-tile 64 (128B rows), 2-stage cp.async, row-XOR swizzle, ldmatrix.x4.
// HALF_OUT=0: f32 C.  HALF_OUT=1: fp16 C (same layout).
// ---------------------------------------------------------------------------
#define SWB2(row, b) ((row) * 128 + (((((b) >> 4) ^ ((row) & 7)) << 4) | ((b) & 15)))
#define GSTAGE 16384
#define GSMEM_TOTAL (4 * GSTAGE)

template <int HALF_OUT>
__global__ __launch_bounds__(256) void gemm_h(const __half* __restrict__ A,
                                              const __half* __restrict__ B,
                                              float* __restrict__ C,
                                              __half* __restrict__ Ch,
                                              int M, int N, int K) {
    extern __shared__ __align__(16) char gsm[];

    const int tid  = threadIdx.x;
    const int lane = tid & 31;
    const int wid  = tid >> 5;
    const int wm   = wid >> 2;
    const int wn   = wid & 3;
    const int g    = lane >> 2;
    const int t    = lane & 3;
    const int row0 = blockIdx.y * 128;
    const int col0 = blockIdx.x * 128;

    const uint32_t smb = (uint32_t)__cvta_generic_to_shared(gsm);
    const uint32_t asb = smb;
    const uint32_t bsb = smb + 2 * GSTAGE;

    uint32_t st[4];
    const __half *Ap[4], *Bp[4];
#pragma unroll
    for (int i = 0; i < 4; i++) {
        const int idx = tid + i * 256;
        const int r   = idx >> 3;
        const int ch  = idx & 7;
        st[i] = SWB2(r, ch * 16);
        Ap[i] = A + (size_t)(row0 + r) * K + ch * 8;
        Bp[i] = B + (size_t)(col0 + r) * K + ch * 8;
    }

    const int a_r = wm * 64 + ((lane >> 3) & 1) * 8 + (lane & 7);
    const int a_c = (lane >> 4) * 16;
    const int b_r = wn * 32 + (lane >> 4) * 8 + (lane & 7);
    const int b_c = ((lane >> 3) & 1) * 16;

    float acc[4][4][4];
#pragma unroll
    for (int mi = 0; mi < 4; mi++)
#pragma unroll
        for (int ni = 0; ni < 4; ni++)
#pragma unroll
            for (int e = 0; e < 4; e++) acc[mi][ni][e] = 0.f;

#pragma unroll
    for (int i = 0; i < 4; i++) {
        cp16(asb + st[i], Ap[i]);
        cp16(bsb + st[i], Bp[i]);
    }
    CP_COMMIT();

    const int NT = K / 64;
    int buf = 0;
    for (int it = 0; it < NT; it++) {
        CP_WAIT0();
        __syncthreads();

        if (it + 1 < NT) {
            const int k0 = (it + 1) * 64;
            const uint32_t sb = (buf ^ 1) * GSTAGE;
#pragma unroll
            for (int i = 0; i < 4; i++) {
                cp16(asb + sb + st[i], Ap[i] + k0);
                cp16(bsb + sb + st[i], Bp[i] + k0);
            }
            CP_COMMIT();
        }

        const uint32_t ab = asb + buf * GSTAGE;
        const uint32_t bb = bsb + buf * GSTAGE;
#pragma unroll
        for (int kk2 = 0; kk2 < 4; kk2++) {
            const int kb = kk2 * 32;
            uint32_t af[4][4], bf[2][4];
#pragma unroll
            for (int mi = 0; mi < 4; mi++)
                ldsm_x4(af[mi], ab + SWB2(a_r + mi * 16, kb + a_c));
#pragma unroll
            for (int np = 0; np < 2; np++)
                ldsm_x4(bf[np], bb + SWB2(b_r + np * 16, kb + b_c));
#pragma unroll
            for (int mi = 0; mi < 4; mi++)
#pragma unroll
                for (int ni = 0; ni < 4; ni++)
                    mma_f16(acc[mi][ni], af[mi],
                            bf[ni >> 1][(ni & 1) * 2], bf[ni >> 1][(ni & 1) * 2 + 1]);
        }
        buf ^= 1;
    }

#pragma unroll
    for (int mi = 0; mi < 4; mi++) {
        const int row = row0 + wm * 64 + mi * 16 + g;
#pragma unroll
        for (int ni = 0; ni < 4; ni++) {
            const int col = col0 + wn * 32 + ni * 8 + 2 * t;
            if (HALF_OUT) {
                *(__half2*)&Ch[(size_t)row * N + col] =
                    __floats2half2_rn(acc[mi][ni][0], acc[mi][ni][1]);
                *(__half2*)&Ch[(size_t)(row + 8) * N + col] =
                    __floats2half2_rn(acc[mi][ni][2], acc[mi][ni][3]);
            } else {
                *(float2*)&C[(size_t)row * N + col] =
                    make_float2(acc[mi][ni][0], acc[mi][ni][1]);
                *(float2*)&C[(size_t)(row + 8) * N + col] =
                    make_float2(acc[mi][ni][2], acc[mi][ni][3]);
            }
        }
    }
}

// ---------------------------------------------------------------------------
// RoPE on fp16 qkv -> fp16 attention tensors.
// ---------------------------------------------------------------------------
#define QSCALE 0.18033688011112042f   // 0.125 * log2(e)

__global__ __launch_bounds__(256) void rope_fp16(const __half* __restrict__ qkv,
                                                 const float* __restrict__ fc,
                                                 __half* __restrict__ Qh,
                                                 __half* __restrict__ Kh,
                                                 __half* __restrict__ Vth) {
    const int s   = blockIdx.x;
    const int tid = threadIdx.x;
    const __half* row = qkv + (size_t)s * QKV_N;

    for (int i = tid; i < NH * (HD / 2); i += 256) {
        int h = i >> 5, d2 = i & 31;
        __half2 x = *(const __half2*)&row[h * HD + 2 * d2];
        float x0 = __low2float(x), x1 = __high2float(x);
        float c  = fc[s * HD + 2 * d2];
        float sn = fc[s * HD + 2 * d2 + 1];
        float y0 = (x0 * c - x1 * sn) * QSCALE;
        float y1 = (x1 * c + x0 * sn) * QSCALE;
        *(__half2*)&Qh[((size_t)h * S + s) * HD + 2 * d2] = __floats2half2_rn(y0, y1);
    }
    {
        int h = tid >> 5, d2 = tid & 31;
        __half2 x = *(const __half2*)&row[D + h * HD + 2 * d2];
        float x0 = __low2float(x), x1 = __high2float(x);
        float c  = fc[s * HD + 2 * d2];
        float sn = fc[s * HD + 2 * d2 + 1];
        float y0 = x0 * c - x1 * sn;
        float y1 = x1 * c + x0 * sn;
        *(__half2*)&Kh[((size_t)h * S + s) * HD + 2 * d2] = __floats2half2_rn(y0, y1);
    }
    for (int i = tid; i < NKV * HD; i += 256) {
        int h = i >> 6, d = i & 63;
        Vth[((size_t)h * HD + d) * S + s] = row[D + NKV * HD + i];
    }
}

// ---------------------------------------------------------------------------
// Tensor-core causal flash attention (fp16 mma, fp32 acc, no-max softmax).
// cp.async double-buffered 64-row K/V tiles, ldmatrix.x4 fragment loads.
// Flat grid with global LPT ordering: all heaviest q-tiles first.
// ---------------------------------------------------------------------------
#define AQ 128
#define AK 64
#define KLD 88   // half stride: 176B; ldmatrix phases + cp.async conflict-free

__global__ __launch_bounds__(256) void attn_mma(const __half* __restrict__ Qh,
                                                const __half* __restrict__ Kh,
                                                const __half* __restrict__ Vth,
                                                __half* __restrict__ O) {
    __shared__ __align__(16) __half Ks[2][AK][KLD];
    __shared__ __align__(16) __half Vs[2][HD][KLD];

    // LPT schedule: bid 0..31 -> qb=15 (heaviest) across all heads, then qb=14...
    const int bid  = blockIdx.x;
    const int qb   = (S / AQ - 1) - (bid >> 5);
    const int h    = bid & 31;
    const int kh   = h >> 2;
    const int tid  = threadIdx.x;
    const int lane = tid & 31;
    const int w    = tid >> 5;
    const int g    = lane >> 2;
    const int t    = lane & 3;
    const int bq   = qb * AQ + w * 16;

    const uint32_t ksb = (uint32_t)__cvta_generic_to_shared(&Ks[0][0][0]);
    const uint32_t vsb = (uint32_t)__cvta_generic_to_shared(&Vs[0][0][0]);
    const uint32_t KBUF = AK * KLD * 2;

    const int f_r = (lane >> 4) * 8 + (lane & 7);
    const int f_c = ((lane >> 3) & 1) * 16;

    uint32_t qf[4][4];
    const __half* Qr0 = Qh + ((size_t)h * S + bq + g) * HD;
    const __half* Qr8 = Qr0 + 8 * HD;
#pragma unroll
    for (int kc = 0; kc < 4; kc++) {
        qf[kc][0] = *(const uint32_t*)(Qr0 + 16 * kc + 2 * t);
        qf[kc][1] = *(const uint32_t*)(Qr8 + 16 * kc + 2 * t);
        qf[kc][2] = *(const uint32_t*)(Qr0 + 16 * kc + 2 * t + 8);
        qf[kc][3] = *(const uint32_t*)(Qr8 + 16 * kc + 2 * t + 8);
    }

    float o[8][4];
#pragma unroll
    for (int nn = 0; nn < 8; nn++)
#pragma unroll
        for (int e = 0; e < 4; e++) o[nn][e] = 0.f;
    float lacc[4] = {0.f, 0.f, 0.f, 0.f};
    const uint32_t ONES = 0x3C003C00u;

    const int ntiles = (qb + 1) * (AQ / AK);

    // prologue: tile 0 -> buf 0
    {
        const __half* Kg = Kh + (size_t)kh * S * HD;
        const __half* Vg = Vth + (size_t)kh * HD * S;
#pragma unroll
        for (int i = 0; i < 2; i++) {
            const int idx = tid + i * 256;
            const int r = idx >> 3, cb = (idx & 7) * 16;
            const uint32_t doff = r * (KLD * 2) + cb;
            cp16(ksb + doff, Kg + (size_t)r * HD + cb / 2);
            cp16(vsb + doff, Vg + (size_t)r * S + cb / 2);
        }
        CP_COMMIT();
    }

    int buf = 0;
    for (int tt = 0; tt < ntiles; tt++) {
        const int kv0 = tt * AK;
        CP_WAIT0();
        __syncthreads();

        if (tt + 1 < ntiles) {
            const int nkv = (tt + 1) * AK;
            const __half* Kg = Kh + (size_t)kh * S * HD + (size_t)nkv * HD;
            const __half* Vg = Vth + (size_t)kh * HD * S + nkv;
            const uint32_t nb = (buf ^ 1) * KBUF;
#pragma unroll
            for (int i = 0; i < 2; i++) {
                const int idx = tid + i * 256;
                const int r = idx >> 3, cb = (idx & 7) * 16;
                const uint32_t doff = nb + r * (KLD * 2) + cb;
                cp16(ksb + doff, Kg + (size_t)r * HD + cb / 2);
                cp16(vsb + doff, Vg + (size_t)r * S + cb / 2);
            }
            CP_COMMIT();
        }

        if (kv0 <= bq + 15) {
            const uint32_t kb0 = ksb + buf * KBUF;
            const uint32_t vb0 = vsb + buf * KBUF;
            float sc[8][4];
#pragma unroll
            for (int nn = 0; nn < 8; nn++)
                sc[nn][0] = sc[nn][1] = sc[nn][2] = sc[nn][3] = 0.f;
#pragma unroll
            for (int kc = 0; kc < 4; kc++) {
                uint32_t bf[4][4];
#pragma unroll
                for (int np = 0; np < 4; np++)
                    ldsm_x4(bf[np], kb0 + (np * 16 + f_r) * (KLD * 2) + kc * 32 + f_c);
#pragma unroll
                for (int nn = 0; nn < 8; nn++)
                    mma_f16(sc[nn], qf[kc],
                            bf[nn >> 1][(nn & 1) * 2], bf[nn >> 1][(nn & 1) * 2 + 1]);
            }
            if (kv0 + AK - 1 > bq) {
                const int rg  = bq + g;
                const int rg8 = rg + 8;
#pragma unroll
                for (int nn = 0; nn < 8; nn++) {
                    const int col = kv0 + nn * 8 + 2 * t;
                    if (col     > rg ) sc[nn][0] = -30.f;
                    if (col + 1 > rg ) sc[nn][1] = -30.f;
                    if (col     > rg8) sc[nn][2] = -30.f;
                    if (col + 1 > rg8) sc[nn][3] = -30.f;
                }
            }
            uint32_t p[8][2];
#pragma unroll
            for (int nn = 0; nn < 8; nn++) {
                p[nn][0] = ex2_h2(pack_h2(sc[nn][0], sc[nn][1]));
                p[nn][1] = ex2_h2(pack_h2(sc[nn][2], sc[nn][3]));
            }
#pragma unroll
            for (int c = 0; c < 4; c++) {
                uint32_t a[4] = {p[2 * c][0], p[2 * c][1],
                                 p[2 * c + 1][0], p[2 * c + 1][1]};
                mma_f16(lacc, a, ONES, ONES);
                uint32_t bf[4][4];
#pragma unroll
                for (int np = 0; np < 4; np++)
                    ldsm_x4(bf[np], vb0 + (np * 16 + f_r) * (KLD * 2) + c * 32 + f_c);
#pragma unroll
                for (int nn = 0; nn < 8; nn++)
                    mma_f16(o[nn], a,
                            bf[nn >> 1][(nn & 1) * 2], bf[nn >> 1][(nn & 1) * 2 + 1]);
            }
        }
        buf ^= 1;
    }

    const float invg  = 1.f / lacc[0];
    const float invg8 = 1.f / lacc[2];
#pragma unroll
    for (int nn = 0; nn < 8; nn++) {
        const int col = h * HD + nn * 8 + 2 * t;
        *(__half2*)&O[(size_t)(bq + g) * D + col] =
            __floats2half2_rn(o[nn][0] * invg, o[nn][1] * invg);
        *(__half2*)&O[(size_t)(bq + g + 8) * D + col] =
            __floats2half2_rn(o[nn][2] * invg8, o[nn][3] * invg8);
    }
}

// ---------------------------------------------------------------------------
// Launch
// ---------------------------------------------------------------------------
extern "C" void kernel_launch(void* const* d_in, const int* in_sizes, int n_in,
                              void* d_out, int out_size) {
    const float* hs   = (const float*)d_in[0];   // [1, 2048, 2048]
    const float* fc   = (const float*)d_in[1];   // [2048, 32, 2]
    const float* wqkv = (const float*)d_in[2];   // [3072, 2048]
    const float* wo   = (const float*)d_in[3];   // [2048, 2048]
    float* out = (float*)d_out;                  // [1, 2048, 2048]

    __half *p_qkvh, *p_hsh, *p_wqkvh, *p_woh, *p_qh, *p_kh, *p_vth, *p_attnh;
    cudaGetSymbolAddress((void**)&p_qkvh,  g_qkvh);
    cudaGetSymbolAddress((void**)&p_hsh,   g_hsh);
    cudaGetSymbolAddress((void**)&p_wqkvh, g_wqkvh);
    cudaGetSymbolAddress((void**)&p_woh,   g_woh);
    cudaGetSymbolAddress((void**)&p_qh,    g_qh);
    cudaGetSymbolAddress((void**)&p_kh,    g_kh);
    cudaGetSymbolAddress((void**)&p_vth,   g_vth);
    cudaGetSymbolAddress((void**)&p_attnh, g_attnh);

    cudaFuncSetAttribute(gemm_h<0>, cudaFuncAttributeMaxDynamicSharedMemorySize,
                         GSMEM_TOTAL);
    cudaFuncSetAttribute(gemm_h<1>, cudaFuncAttributeMaxDynamicSharedMemorySize,
                         GSMEM_TOTAL);

    // 0) fp16 conversions (single fused kernel)
    cvt_all<<<(N4_ALL + 255) / 256, 256>>>(hs, wqkv, wo, p_hsh, p_wqkvh, p_woh);

    // 1) qkv = hs @ wqkv^T  (fp16 out)
    gemm_h<1><<<dim3(QKV_N / 128, S / 128), 256, GSMEM_TOTAL>>>(
        p_hsh, p_wqkvh, nullptr, p_qkvh, S, QKV_N, D);
    // 2) RoPE -> fp16 Q (pre-scaled), K, V^T
    rope_fp16<<<S, 256>>>(p_qkvh, fc, p_qh, p_kh, p_vth);
    // 3) tensor-core causal attention (fp16 out), LPT-ordered flat grid
    attn_mma<<<(S / AQ) * NH, 256>>>(p_qh, p_kh, p_vth, p_attnh);
    // 4) out = attn @ wo^T  (f32 out)
    gemm_h<0><<<dim3(D / 128, S / 128), 256, GSMEM_TOTAL>>>(
        p_attnh, p_woh, out, nullptr, S, D, D);
}

// round 17
// speedup vs baseline: 1.1313x; 1.0295x over previous
#include <cuda_runtime.h>
#include <cuda_fp16.h>
#include <math.h>
#include <stdint.h>

// Problem constants
#define S    2048
#define D    2048
#define NH   32
#define NKV  8
#define HD   64
#define QKV_N 3072   // (32 + 16) * 64
#define VOFF (D + NKV * HD)   // 2560: V section start in qkv row

// ---------------------------------------------------------------------------
// Scratch (device globals — no allocation allowed)
// ---------------------------------------------------------------------------
__device__ __half g_qkvh [(size_t)S * QKV_N];     // [s, 3072] fp16 qkv
__device__ __half g_hsh  [(size_t)S * D];         // hs in fp16
__device__ __half g_wqkvh[(size_t)QKV_N * D];     // wqkv in fp16
__device__ __half g_woh  [(size_t)D * D];         // wo in fp16
__device__ __half g_kh [(size_t)NKV * S * HD];    // [kh, s, d] (rope'd K)
__device__ __half g_attnh[(size_t)S * D];         // attention out, fp16

__device__ __forceinline__ void mma_f16(float* d, const uint32_t* a,
                                        uint32_t b0, uint32_t b1) {
    asm volatile(
        "mma.sync.aligned.m16n8k16.row.col.f32.f16.f16.f32 "
        "{%0,%1,%2,%3}, {%4,%5,%6,%7}, {%8,%9}, {%0,%1,%2,%3};"
        : "+f"(d[0]), "+f"(d[1]), "+f"(d[2]), "+f"(d[3])
        : "r"(a[0]), "r"(a[1]), "r"(a[2]), "r"(a[3]), "r"(b0), "r"(b1));
}

__device__ __forceinline__ void ldsm_x4(uint32_t* r, uint32_t addr) {
    asm volatile("ldmatrix.sync.aligned.m8n8.x4.shared.b16 {%0,%1,%2,%3}, [%4];"
                 : "=r"(r[0]), "=r"(r[1]), "=r"(r[2]), "=r"(r[3]) : "r"(addr));
}

__device__ __forceinline__ void ldsm_x4_t(uint32_t* r, uint32_t addr) {
    asm volatile("ldmatrix.sync.aligned.m8n8.x4.trans.shared.b16 {%0,%1,%2,%3}, [%4];"
                 : "=r"(r[0]), "=r"(r[1]), "=r"(r[2]), "=r"(r[3]) : "r"(addr));
}

__device__ __forceinline__ void cp16(uint32_t dst, const void* src) {
    asm volatile("cp.async.cg.shared.global [%0], [%1], 16;" :: "r"(dst), "l"(src));
}
#define CP_COMMIT() asm volatile("cp.async.commit_group;" ::: "memory")
#define CP_WAIT0()  asm volatile("cp.async.wait_group 0;" ::: "memory")

__device__ __forceinline__ uint32_t ex2_h2(uint32_t x) {
    uint32_t r;
    asm("ex2.approx.f16x2 %0, %1;" : "=r"(r) : "r"(x));
    return r;
}
__device__ __forceinline__ uint32_t pack_h2(float lo, float hi) {
    __half2 h = __floats2half2_rn(lo, hi);
    return *(uint32_t*)&h;
}

// ---------------------------------------------------------------------------
// fused f32 -> f16 conversion of hs, wqkv, wo
// ---------------------------------------------------------------------------
#define N4_HS   (S * D / 4)
#define N4_WQKV (QKV_N * D / 4)
#define N4_WO   (D * D / 4)
#define N4_ALL  (N4_HS + N4_WQKV + N4_WO)

__global__ __launch_bounds__(256) void cvt_all(const float* __restrict__ hs,
                                               const float* __restrict__ wqkv,
                                               const float* __restrict__ wo,
                                               __half* __restrict__ hsh,
                                               __half* __restrict__ wqkvh,
                                               __half* __restrict__ woh) {
    int i = blockIdx.x * 256 + threadIdx.x;
    const float* src;
    __half* dst;
    int j;
    if (i < N4_HS)                   { src = hs;   dst = hsh;   j = i; }
    else if (i < N4_HS + N4_WQKV)    { src = wqkv; dst = wqkvh; j = i - N4_HS; }
    else if (i < N4_ALL)             { src = wo;   dst = woh;   j = i - N4_HS - N4_WQKV; }
    else return;
    float4 v = ((const float4*)src)[j];
    __half2 h01 = __floats2half2_rn(v.x, v.y);
    __half2 h23 = __floats2half2_rn(v.z, v.w);
    ((uint2*)dst)[j] = make_uint2(*(uint32_t*)&h01, *(uint32_t*)&h23);
}

// ---------------------------------------------------------------------------
// fp16 tensor-core GEMM: CTA 128x128, 8 warps (2m x 4n), warp tile 64x32,
// k-tile 64 (128B rows), 2-stage cp.async, row-XOR swizzle, ldmatrix.x4.
// HALF_OUT=0: f32 C.  HALF_OUT=1: fp16 C.
// ---------------------------------------------------------------------------
#define SWB2(row, b) ((row) * 128 + (((((b) >> 4) ^ ((row) & 7)) << 4) | ((b) & 15)))
#define GSTAGE 16384
#define GSMEM_TOTAL (4 * GSTAGE)

template <int HALF_OUT>
__global__ __launch_bounds__(256) void gemm_h(const __half* __restrict__ A,
                                              const __half* __restrict__ B,
                                              float* __restrict__ C,
                                              __half* __restrict__ Ch,
                                              int M, int N, int K) {
    extern __shared__ __align__(16) char gsm[];

    const int tid  = threadIdx.x;
    const int lane = tid & 31;
    const int wid  = tid >> 5;
    const int wm   = wid >> 2;
    const int wn   = wid & 3;
    const int g    = lane >> 2;
    const int t    = lane & 3;
    const int row0 = blockIdx.y * 128;
    const int col0 = blockIdx.x * 128;

    const uint32_t smb = (uint32_t)__cvta_generic_to_shared(gsm);
    const uint32_t asb = smb;
    const uint32_t bsb = smb + 2 * GSTAGE;

    uint32_t st[4];
    const __half *Ap[4], *Bp[4];
#pragma unroll
    for (int i = 0; i < 4; i++) {
        const int idx = tid + i * 256;
        const int r   = idx >> 3;
        const int ch  = idx & 7;
        st[i] = SWB2(r, ch * 16);
        Ap[i] = A + (size_t)(row0 + r) * K + ch * 8;
        Bp[i] = B + (size_t)(col0 + r) * K + ch * 8;
    }

    const int a_r = wm * 64 + ((lane >> 3) & 1) * 8 + (lane & 7);
    const int a_c = (lane >> 4) * 16;
    const int b_r = wn * 32 + (lane >> 4) * 8 + (lane & 7);
    const int b_c = ((lane >> 3) & 1) * 16;

    float acc[4][4][4];
#pragma unroll
    for (int mi = 0; mi < 4; mi++)
#pragma unroll
        for (int ni = 0; ni < 4; ni++)
#pragma unroll
            for (int e = 0; e < 4; e++) acc[mi][ni][e] = 0.f;

#pragma unroll
    for (int i = 0; i < 4; i++) {
        cp16(asb + st[i], Ap[i]);
        cp16(bsb + st[i], Bp[i]);
    }
    CP_COMMIT();

    const int NT = K / 64;
    int buf = 0;
    for (int it = 0; it < NT; it++) {
        CP_WAIT0();
        __syncthreads();

        if (it + 1 < NT) {
            const int k0 = (it + 1) * 64;
            const uint32_t sb = (buf ^ 1) * GSTAGE;
#pragma unroll
            for (int i = 0; i < 4; i++) {
                cp16(asb + sb + st[i], Ap[i] + k0);
                cp16(bsb + sb + st[i], Bp[i] + k0);
            }
            CP_COMMIT();
        }

        const uint32_t ab = asb + buf * GSTAGE;
        const uint32_t bb = bsb + buf * GSTAGE;
#pragma unroll
        for (int kk2 = 0; kk2 < 4; kk2++) {
            const int kb = kk2 * 32;
            uint32_t af[4][4], bf[2][4];
#pragma unroll
            for (int mi = 0; mi < 4; mi++)
                ldsm_x4(af[mi], ab + SWB2(a_r + mi * 16, kb + a_c));
#pragma unroll
            for (int np = 0; np < 2; np++)
                ldsm_x4(bf[np], bb + SWB2(b_r + np * 16, kb + b_c));
#pragma unroll
            for (int mi = 0; mi < 4; mi++)
#pragma unroll
                for (int ni = 0; ni < 4; ni++)
                    mma_f16(acc[mi][ni], af[mi],
                            bf[ni >> 1][(ni & 1) * 2], bf[ni >> 1][(ni & 1) * 2 + 1]);
        }
        buf ^= 1;
    }

#pragma unroll
    for (int mi = 0; mi < 4; mi++) {
        const int row = row0 + wm * 64 + mi * 16 + g;
#pragma unroll
        for (int ni = 0; ni < 4; ni++) {
            const int col = col0 + wn * 32 + ni * 8 + 2 * t;
            if (HALF_OUT) {
                *(__half2*)&Ch[(size_t)row * N + col] =
                    __floats2half2_rn(acc[mi][ni][0], acc[mi][ni][1]);
                *(__half2*)&Ch[(size_t)(row + 8) * N + col] =
                    __floats2half2_rn(acc[mi][ni][2], acc[mi][ni][3]);
            } else {
                *(float2*)&C[(size_t)row * N + col] =
                    make_float2(acc[mi][ni][0], acc[mi][ni][1]);
                *(float2*)&C[(size_t)(row + 8) * N + col] =
                    make_float2(acc[mi][ni][2], acc[mi][ni][3]);
            }
        }
    }
}

// ---------------------------------------------------------------------------
// RoPE on K only: qkvh -> Kh [kh, s, d].  One block per sequence position.
// ---------------------------------------------------------------------------
#define QSCALE 0.18033688011112042f   // 0.125 * log2(e)

__global__ __launch_bounds__(256) void rope_k(const __half* __restrict__ qkv,
                                              const float* __restrict__ fc,
                                              __half* __restrict__ Kh) {
    const int s   = blockIdx.x;
    const int tid = threadIdx.x;     // 8 heads * 32 pairs = 256
    const int h   = tid >> 5, d2 = tid & 31;
    __half2 x = *(const __half2*)&qkv[(size_t)s * QKV_N + D + h * HD + 2 * d2];
    float x0 = __low2float(x), x1 = __high2float(x);
    float c  = fc[s * HD + 2 * d2];
    float sn = fc[s * HD + 2 * d2 + 1];
    float y0 = x0 * c - x1 * sn;
    float y1 = x1 * c + x0 * sn;
    *(__half2*)&Kh[((size_t)h * S + s) * HD + 2 * d2] = __floats2half2_rn(y0, y1);
}

// ---------------------------------------------------------------------------
// Tensor-core causal flash attention.
//  - Q read directly from qkvh, RoPE + scale applied in registers.
//  - K tiles from Kh (rope'd), V tiles direct from qkvh (same [kv][d] layout);
//    V^T fragments obtained with ldmatrix.trans.
//  - LPT flat grid, cp.async double buffering, no-max softmax via ex2.f16x2.
// ---------------------------------------------------------------------------
#define AQ 128
#define AK 64
#define KLD 88   // half stride: 176B; conflict-free for ldsm + ldsm.trans

__global__ __launch_bounds__(256) void attn_mma(const __half* __restrict__ qkvh,
                                                const __half* __restrict__ Kh,
                                                const float* __restrict__ fc,
                                                __half* __restrict__ O) {
    __shared__ __align__(16) __half Ks[2][AK][KLD];
    __shared__ __align__(16) __half Vs[2][AK][KLD];   // [kv][d], same as K

    // LPT schedule: heaviest q-tiles first across all heads
    const int bid  = blockIdx.x;
    const int qb   = (S / AQ - 1) - (bid >> 5);
    const int h    = bid & 31;
    const int kh   = h >> 2;
    const int tid  = threadIdx.x;
    const int lane = tid & 31;
    const int w    = tid >> 5;
    const int g    = lane >> 2;
    const int t    = lane & 3;
    const int bq   = qb * AQ + w * 16;

    const uint32_t ksb = (uint32_t)__cvta_generic_to_shared(&Ks[0][0][0]);
    const uint32_t vsb = (uint32_t)__cvta_generic_to_shared(&Vs[0][0][0]);
    const uint32_t KBUF = AK * KLD * 2;

    // ldmatrix geometry: K (B-frag, non-trans) and V (B-frag via trans)
    const int f_r = (lane >> 4) * 8 + (lane & 7);
    const int f_c = ((lane >> 3) & 1) * 16;
    const int v_r = ((lane >> 3) & 1) * 8 + (lane & 7);   // kv row within 16-chunk
    const int v_c = (lane >> 4) * 16;                     // d byte chunk (0/16)

    // --- Q fragments: load raw from qkvh, apply RoPE + QSCALE in registers ---
    uint32_t qf[4][4];
    {
        const __half* Q0 = qkvh + (size_t)(bq + g) * QKV_N + h * HD;
        const __half* Q8 = Q0 + 8 * QKV_N;
        const float*  F0 = fc + (size_t)(bq + g) * HD;
        const float*  F8 = F0 + 8 * HD;
#pragma unroll
        for (int kc = 0; kc < 4; kc++) {
#pragma unroll
            for (int j = 0; j < 4; j++) {
                const int col = 16 * kc + 2 * t + (j >> 1) * 8;
                const __half* qp = (j & 1) ? Q8 : Q0;
                const float*  fp = (j & 1) ? F8 : F0;
                __half2 x = *(const __half2*)(qp + col);
                float x0 = __low2float(x), x1 = __high2float(x);
                float2 cs = *(const float2*)(fp + col);
                qf[kc][j] = pack_h2((x0 * cs.x - x1 * cs.y) * QSCALE,
                                    (x1 * cs.x + x0 * cs.y) * QSCALE);
            }
        }
    }

    float o[8][4];
#pragma unroll
    for (int nn = 0; nn < 8; nn++)
#pragma unroll
        for (int e = 0; e < 4; e++) o[nn][e] = 0.f;
    float lacc[4] = {0.f, 0.f, 0.f, 0.f};
    const uint32_t ONES = 0x3C003C00u;

    const int ntiles = (qb + 1) * (AQ / AK);
    const __half* Kg = Kh + (size_t)kh * S * HD;            // [kv][64]
    const __half* Vg = qkvh + VOFF + kh * HD;               // row kv: + kv*3072

    // prologue: tile 0 -> buf 0
    {
#pragma unroll
        for (int i = 0; i < 2; i++) {
            const int idx = tid + i * 256;
            const int r = idx >> 3, cb = (idx & 7) * 16;
            const uint32_t doff = r * (KLD * 2) + cb;
            cp16(ksb + doff, Kg + (size_t)r * HD + cb / 2);
            cp16(vsb + doff, Vg + (size_t)r * QKV_N + cb / 2);
        }
        CP_COMMIT();
    }

    int buf = 0;
    for (int tt = 0; tt < ntiles; tt++) {
        const int kv0 = tt * AK;
        CP_WAIT0();
        __syncthreads();

        if (tt + 1 < ntiles) {
            const int nkv = (tt + 1) * AK;
            const uint32_t nb = (buf ^ 1) * KBUF;
#pragma unroll
            for (int i = 0; i < 2; i++) {
                const int idx = tid + i * 256;
                const int r = idx >> 3, cb = (idx & 7) * 16;
                const uint32_t doff = nb + r * (KLD * 2) + cb;
                cp16(ksb + doff, Kg + (size_t)(nkv + r) * HD + cb / 2);
                cp16(vsb + doff, Vg + (size_t)(nkv + r) * QKV_N + cb / 2);
            }
            CP_COMMIT();
        }

        if (kv0 <= bq + 15) {
            const uint32_t kb0 = ksb + buf * KBUF;
            const uint32_t vb0 = vsb + buf * KBUF;
            float sc[8][4];
#pragma unroll
            for (int nn = 0; nn < 8; nn++)
                sc[nn][0] = sc[nn][1] = sc[nn][2] = sc[nn][3] = 0.f;
#pragma unroll
            for (int kc = 0; kc < 4; kc++) {
                uint32_t bf[4][4];
#pragma unroll
                for (int np = 0; np < 4; np++)
                    ldsm_x4(bf[np], kb0 + (np * 16 + f_r) * (KLD * 2) + kc * 32 + f_c);
#pragma unroll
                for (int nn = 0; nn < 8; nn++)
                    mma_f16(sc[nn], qf[kc],
                            bf[nn >> 1][(nn & 1) * 2], bf[nn >> 1][(nn & 1) * 2 + 1]);
            }
            if (kv0 + AK - 1 > bq) {
                const int rg  = bq + g;
                const int rg8 = rg + 8;
#pragma unroll
                for (int nn = 0; nn < 8; nn++) {
                    const int col = kv0 + nn * 8 + 2 * t;
                    if (col     > rg ) sc[nn][0] = -30.f;
                    if (col + 1 > rg ) sc[nn][1] = -30.f;
                    if (col     > rg8) sc[nn][2] = -30.f;
                    if (col + 1 > rg8) sc[nn][3] = -30.f;
                }
            }
            uint32_t p[8][2];
#pragma unroll
            for (int nn = 0; nn < 8; nn++) {
                p[nn][0] = ex2_h2(pack_h2(sc[nn][0], sc[nn][1]));
                p[nn][1] = ex2_h2(pack_h2(sc[nn][2], sc[nn][3]));
            }
            // P @ V with V^T frags via ldmatrix.trans on [kv][d] tiles
#pragma unroll
            for (int c = 0; c < 4; c++) {
                uint32_t a[4] = {p[2 * c][0], p[2 * c][1],
                                 p[2 * c + 1][0], p[2 * c + 1][1]};
                mma_f16(lacc, a, ONES, ONES);
                uint32_t bf[4][4];
#pragma unroll
                for (int np = 0; np < 4; np++)
                    ldsm_x4_t(bf[np], vb0 + (c * 16 + v_r) * (KLD * 2) + np * 32 + v_c);
#pragma unroll
                for (int nn = 0; nn < 8; nn++)
                    mma_f16(o[nn], a,
                            bf[nn >> 1][(nn & 1) * 2], bf[nn >> 1][(nn & 1) * 2 + 1]);
            }
        }
        buf ^= 1;
    }

    const float invg  = 1.f / lacc[0];
    const float invg8 = 1.f / lacc[2];
#pragma unroll
    for (int nn = 0; nn < 8; nn++) {
        const int col = h * HD + nn * 8 + 2 * t;
        *(__half2*)&O[(size_t)(bq + g) * D + col] =
            __floats2half2_rn(o[nn][0] * invg, o[nn][1] * invg);
        *(__half2*)&O[(size_t)(bq + g + 8) * D + col] =
            __floats2half2_rn(o[nn][2] * invg8, o[nn][3] * invg8);
    }
}

// ---------------------------------------------------------------------------
// Launch
// ---------------------------------------------------------------------------
extern "C" void kernel_launch(void* const* d_in, const int* in_sizes, int n_in,
                              void* d_out, int out_size) {
    const float* hs   = (const float*)d_in[0];   // [1, 2048, 2048]
    const float* fc   = (const float*)d_in[1];   // [2048, 32, 2]
    const float* wqkv = (const float*)d_in[2];   // [3072, 2048]
    const float* wo   = (const float*)d_in[3];   // [2048, 2048]
    float* out = (float*)d_out;                  // [1, 2048, 2048]

    __half *p_qkvh, *p_hsh, *p_wqkvh, *p_woh, *p_kh, *p_attnh;
    cudaGetSymbolAddress((void**)&p_qkvh,  g_qkvh);
    cudaGetSymbolAddress((void**)&p_hsh,   g_hsh);
    cudaGetSymbolAddress((void**)&p_wqkvh, g_wqkvh);
    cudaGetSymbolAddress((void**)&p_woh,   g_woh);
    cudaGetSymbolAddress((void**)&p_kh,    g_kh);
    cudaGetSymbolAddress((void**)&p_attnh, g_attnh);

    cudaFuncSetAttribute(gemm_h<0>, cudaFuncAttributeMaxDynamicSharedMemorySize,
                         GSMEM_TOTAL);
    cudaFuncSetAttribute(gemm_h<1>, cudaFuncAttributeMaxDynamicSharedMemorySize,
                         GSMEM_TOTAL);

    // 0) fp16 conversions (single fused kernel)
    cvt_all<<<(N4_ALL + 255) / 256, 256>>>(hs, wqkv, wo, p_hsh, p_wqkvh, p_woh);

    // 1) qkv = hs @ wqkv^T  (fp16 out)
    gemm_h<1><<<dim3(QKV_N / 128, S / 128), 256, GSMEM_TOTAL>>>(
        p_hsh, p_wqkvh, nullptr, p_qkvh, S, QKV_N, D);
    // 2) RoPE K only
    rope_k<<<S, 256>>>(p_qkvh, fc, p_kh);
    // 3) tensor-core causal attention (Q rope'd in-register, V direct)
    attn_mma<<<(S / AQ) * NH, 256>>>(p_qkvh, p_kh, fc, p_attnh);
    // 4) out = attn @ wo^T  (f32 out)
    gemm_h<0><<<dim3(D / 128, S / 128), 256, GSMEM_TOTAL>>>(
        p_attnh, p_woh, out, nullptr, S, D, D);
}